// round 9
// baseline (speedup 1.0000x reference)
#include <cuda_runtime.h>
#include <cuda_bf16.h>
#include <math.h>
#include <stdint.h>

// ---------------------------------------------------------------------------
#define R_ROWS   4096
#define HIDDEN   1024
#define QKVFF    7168
#define VFF      5120
#define LSEQ     2048
#define NHEADS   16
#define HDIM     64
#define LN_EPS   1e-5f

// ---------------------------------------------------------------------------
// Device scratch
// ---------------------------------------------------------------------------
__device__ float g_h[(size_t)R_ROWS * QKVFF];
__device__ __nv_bfloat16 g_A1hi[(size_t)R_ROWS * HIDDEN];
__device__ __nv_bfloat16 g_A1lo[(size_t)R_ROWS * HIDDEN];
__device__ __nv_bfloat16 g_B1hi[(size_t)QKVFF * HIDDEN];
__device__ __nv_bfloat16 g_B1lo[(size_t)QKVFF * HIDDEN];
__device__ __nv_bfloat16 g_A2hi[(size_t)R_ROWS * VFF];
__device__ __nv_bfloat16 g_A2lo[(size_t)R_ROWS * VFF];
__device__ __nv_bfloat16 g_B2hi[(size_t)HIDDEN * VFF];
__device__ __nv_bfloat16 g_B2lo[(size_t)HIDDEN * VFF];
__device__ __nv_bfloat16 g_Qhi[(size_t)32 * LSEQ * HDIM];
__device__ __nv_bfloat16 g_Qlo[(size_t)32 * LSEQ * HDIM];
__device__ __nv_bfloat16 g_Khi[(size_t)32 * LSEQ * HDIM];
__device__ __nv_bfloat16 g_Klo[(size_t)32 * LSEQ * HDIM];
__device__ __nv_bfloat16 g_Vthi[(size_t)32 * HDIM * LSEQ];
__device__ __nv_bfloat16 g_Vtlo[(size_t)32 * HDIM * LSEQ];

// ---------------------------------------------------------------------------
// helpers
// ---------------------------------------------------------------------------
static __device__ __forceinline__ uint32_t smem_u32(const void* p) {
    uint32_t a;
    asm("{ .reg .u64 t; cvta.to.shared.u64 t, %1; cvt.u32.u64 %0, t; }"
        : "=r"(a) : "l"(p));
    return a;
}
static __device__ __forceinline__ void fsplit(float v, __nv_bfloat16& hi, __nv_bfloat16& lo) {
    hi = __float2bfloat16(v);
    lo = __float2bfloat16(v - __bfloat162float(hi));
}
static __device__ __forceinline__ uint32_t pack_bf16x2(float lo, float hi) {
    uint32_t r;
    asm("cvt.rn.bf16x2.f32 %0, %1, %2;" : "=r"(r) : "f"(hi), "f"(lo));
    return r;
}

#define CP_ASYNC16(dst, src) \
    asm volatile("cp.async.cg.shared.global [%0], [%1], 16;" :: "r"(dst), "l"(src) : "memory")
#define CP_COMMIT() asm volatile("cp.async.commit_group;" ::: "memory")
#define CP_WAIT1()  asm volatile("cp.async.wait_group 1;" ::: "memory")
#define CP_WAIT0()  asm volatile("cp.async.wait_group 0;" ::: "memory")

#define LDM_X4(r0, r1, r2, r3, addr)                                          \
    asm volatile("ldmatrix.sync.aligned.m8n8.x4.shared.b16 {%0,%1,%2,%3}, [%4];" \
                 : "=r"(r0), "=r"(r1), "=r"(r2), "=r"(r3) : "r"(addr))

static __device__ __forceinline__ void mma_bf16(float* d, const uint32_t* a,
                                                const uint32_t* b) {
    asm volatile(
        "mma.sync.aligned.m16n8k16.row.col.f32.bf16.bf16.f32 "
        "{%0,%1,%2,%3}, {%4,%5,%6,%7}, {%8,%9}, {%0,%1,%2,%3};"
        : "+f"(d[0]), "+f"(d[1]), "+f"(d[2]), "+f"(d[3])
        : "r"(a[0]), "r"(a[1]), "r"(a[2]), "r"(a[3]), "r"(b[0]), "r"(b[1]));
}

// ---------------------------------------------------------------------------
// 1) LayerNorm -> bf16 hi/lo operand A1
// ---------------------------------------------------------------------------
__global__ __launch_bounds__(256)
void ln_kernel(const float* __restrict__ x, const float* __restrict__ w,
               const float* __restrict__ b,
               __nv_bfloat16* __restrict__ a_hi, __nv_bfloat16* __restrict__ a_lo) {
    int row = blockIdx.x;
    const float* xr = x + (size_t)row * HIDDEN;
    int tid = threadIdx.x;

    float4 v = *(const float4*)(xr + tid * 4);
    float s  = v.x + v.y + v.z + v.w;
    float s2 = v.x * v.x + v.y * v.y + v.z * v.z + v.w * v.w;
    for (int off = 16; off >= 1; off >>= 1) {
        s  += __shfl_xor_sync(0xffffffffu, s,  off);
        s2 += __shfl_xor_sync(0xffffffffu, s2, off);
    }
    __shared__ float ws[8], ws2[8];
    int wid = tid >> 5, lid = tid & 31;
    if (lid == 0) { ws[wid] = s; ws2[wid] = s2; }
    __syncthreads();
    if (wid == 0) {
        float a  = (lid < 8) ? ws[lid]  : 0.f;
        float a2 = (lid < 8) ? ws2[lid] : 0.f;
        for (int off = 4; off >= 1; off >>= 1) {
            a  += __shfl_xor_sync(0xffffffffu, a,  off);
            a2 += __shfl_xor_sync(0xffffffffu, a2, off);
        }
        if (lid == 0) { ws[0] = a; ws2[0] = a2; }
    }
    __syncthreads();
    float mu  = ws[0] * (1.0f / HIDDEN);
    float var = ws2[0] * (1.0f / HIDDEN) - mu * mu;
    float rsig = rsqrtf(var + LN_EPS);

    float4 wv = *(const float4*)(w + tid * 4);
    float4 bv = *(const float4*)(b + tid * 4);
    float o0 = (v.x - mu) * rsig * wv.x + bv.x;
    float o1 = (v.y - mu) * rsig * wv.y + bv.y;
    float o2 = (v.z - mu) * rsig * wv.z + bv.z;
    float o3 = (v.w - mu) * rsig * wv.w + bv.w;

    size_t base = (size_t)row * HIDDEN + tid * 4;
    __nv_bfloat16 h0, l0, h1, l1, h2, l2, h3, l3;
    fsplit(o0, h0, l0); fsplit(o1, h1, l1); fsplit(o2, h2, l2); fsplit(o3, h3, l3);
    a_hi[base + 0] = h0; a_hi[base + 1] = h1; a_hi[base + 2] = h2; a_hi[base + 3] = h3;
    a_lo[base + 0] = l0; a_lo[base + 1] = l1; a_lo[base + 2] = l2; a_lo[base + 3] = l3;
}

// ---------------------------------------------------------------------------
// Weight transpose + hi/lo split
// ---------------------------------------------------------------------------
__global__ __launch_bounds__(256)
void convw_kernel(const float* __restrict__ W,
                  __nv_bfloat16* __restrict__ bhi, __nv_bfloat16* __restrict__ blo,
                  int K, int N) {
    __shared__ float t[32][33];
    int n0 = blockIdx.x * 32, k0 = blockIdx.y * 32;
    int tx = threadIdx.x & 31, ty = threadIdx.x >> 5;
    for (int r = ty; r < 32; r += 8)
        t[r][tx] = W[(size_t)(k0 + r) * N + n0 + tx];
    __syncthreads();
    for (int r = ty; r < 32; r += 8) {
        float v = t[tx][r];
        __nv_bfloat16 hi, lo;
        fsplit(v, hi, lo);
        size_t o = (size_t)(n0 + r) * K + k0 + tx;
        bhi[o] = hi; blo[o] = lo;
    }
}

// ---------------------------------------------------------------------------
// mma.sync GEMM — now __launch_bounds__(256, 2): cap 128 regs so 2 CTAs/SM.
// ---------------------------------------------------------------------------
#define GSTAGE   40960
#define GSMEM    (2 * GSTAGE)
#define GSTRIDE  80

__global__ __launch_bounds__(256, 2)
void gemm_mma(const __nv_bfloat16* __restrict__ Ahi, const __nv_bfloat16* __restrict__ Alo,
              const __nv_bfloat16* __restrict__ Bhi, const __nv_bfloat16* __restrict__ Blo,
              float* __restrict__ C, int K, int ldc) {
    extern __shared__ char dsm[];
    uint32_t sb = smem_u32(dsm);

    int tid = threadIdx.x, warp = tid >> 5, lane = tid & 31;
    int m0 = blockIdx.y * 128, n0 = blockIdx.x * 128;
    int warp_m = (warp & 3) * 32, warp_n = (warp >> 2) * 64;

    const __nv_bfloat16* gmat[4] = {Ahi, Alo, Bhi, Blo};

    auto load_stage = [&](int s, int kt) {
        uint32_t stage = sb + s * GSTAGE;
#pragma unroll
        for (int t = 0; t < 8; t++) {
            int idx = t * 256 + tid;
            int mat = idx >> 9;
            int r   = (idx >> 2) & 127;
            int cg  = idx & 3;
            int row0 = (mat < 2) ? m0 : n0;
            const __nv_bfloat16* src = gmat[mat] + (size_t)(row0 + r) * K + kt + cg * 8;
            uint32_t dst = stage + mat * 10240 + r * GSTRIDE + cg * 16;
            CP_ASYNC16(dst, src);
        }
    };

    float acc[2][8][4];
#pragma unroll
    for (int i = 0; i < 2; i++)
#pragma unroll
        for (int j = 0; j < 8; j++)
#pragma unroll
            for (int q = 0; q < 4; q++) acc[i][j][q] = 0.f;

    int NC = K >> 5;
    load_stage(0, 0);
    CP_COMMIT();

    for (int c = 0; c < NC; c++) {
        if (c + 1 < NC) load_stage((c + 1) & 1, (c + 1) * 32);
        CP_COMMIT();
        if (c + 1 < NC) CP_WAIT1(); else CP_WAIT0();
        __syncthreads();

        uint32_t st  = sb + (c & 1) * GSTAGE;
        uint32_t sAh = st, sAl = st + 10240, sBh = st + 20480, sBl = st + 30720;

#pragma unroll
        for (int k16 = 0; k16 < 2; k16++) {
            int k0 = k16 * 16;
            uint32_t ah[2][4], al[2][4];
            {
                int arow = warp_m + (lane & 15);
                int acol = k0 + ((lane >> 4) << 3);
                uint32_t off0 = (uint32_t)(arow * GSTRIDE + acol * 2);
                uint32_t off1 = off0 + 16 * GSTRIDE;
                LDM_X4(ah[0][0], ah[0][1], ah[0][2], ah[0][3], sAh + off0);
                LDM_X4(ah[1][0], ah[1][1], ah[1][2], ah[1][3], sAh + off1);
                LDM_X4(al[0][0], al[0][1], al[0][2], al[0][3], sAl + off0);
                LDM_X4(al[1][0], al[1][1], al[1][2], al[1][3], sAl + off1);
            }
            int brow_l = (lane & 7) + ((lane & 16) >> 1);
            int bcol   = k0 + ((lane >> 3) & 1) * 8;
#pragma unroll
            for (int ng = 0; ng < 4; ng++) {
                uint32_t boff = (uint32_t)((warp_n + ng * 16 + brow_l) * GSTRIDE + bcol * 2);
                uint32_t bh[4], bl[4];
                LDM_X4(bh[0], bh[1], bh[2], bh[3], sBh + boff);
                LDM_X4(bl[0], bl[1], bl[2], bl[3], sBl + boff);
#pragma unroll
                for (int mt = 0; mt < 2; mt++)
#pragma unroll
                    for (int tt = 0; tt < 2; tt++) {
                        int nt = 2 * ng + tt;
                        mma_bf16(acc[mt][nt], ah[mt], &bh[2 * tt]);
                        mma_bf16(acc[mt][nt], al[mt], &bh[2 * tt]);
                        mma_bf16(acc[mt][nt], ah[mt], &bl[2 * tt]);
                    }
            }
        }
        __syncthreads();
    }

    int rbase = m0 + warp_m + (lane >> 2);
    int cbase = n0 + warp_n + (lane & 3) * 2;
#pragma unroll
    for (int mt = 0; mt < 2; mt++)
#pragma unroll
        for (int nt = 0; nt < 8; nt++) {
            int r = rbase + mt * 16;
            int cc = cbase + nt * 8;
            *(float2*)(C + (size_t)r * ldc + cc) =
                make_float2(acc[mt][nt][0], acc[mt][nt][1]);
            *(float2*)(C + (size_t)(r + 8) * ldc + cc) =
                make_float2(acc[mt][nt][2], acc[mt][nt][3]);
        }
}

// ---------------------------------------------------------------------------
// 3) RoPE -> split q/k; GELU(ff) -> A2 cols [1024, 5120)
// ---------------------------------------------------------------------------
__global__ __launch_bounds__(256)
void rope_gelu_kernel(const float* __restrict__ h,
                      __nv_bfloat16* __restrict__ qhi, __nv_bfloat16* __restrict__ qlo,
                      __nv_bfloat16* __restrict__ khi, __nv_bfloat16* __restrict__ klo,
                      __nv_bfloat16* __restrict__ a2hi, __nv_bfloat16* __restrict__ a2lo) {
    int row = blockIdx.x;
    int b = row >> 11, l = row & (LSEQ - 1);
    const float* hr = h + (size_t)row * QKVFF;

    for (int idx = threadIdx.x; idx < NHEADS * 32; idx += 256) {
        int head = idx >> 5, i = idx & 31;
        float invf = (float)exp(-(double)i / 32.0 * log(10000.0));
        float ang = (float)l * invf;
        float c = cosf(ang), s = sinf(ang);
        size_t obase = ((size_t)(b * NHEADS + head) * LSEQ + l) * HDIM + i;

        float q0 = hr[head * HDIM + i], q1 = hr[head * HDIM + i + 32];
        float rq0 = (q0 * c - q1 * s) * 0.125f;
        float rq1 = (q1 * c + q0 * s) * 0.125f;
        __nv_bfloat16 hi, lo;
        fsplit(rq0, hi, lo); qhi[obase] = hi;      qlo[obase] = lo;
        fsplit(rq1, hi, lo); qhi[obase + 32] = hi; qlo[obase + 32] = lo;

        float k0 = hr[HIDDEN + head * HDIM + i], k1 = hr[HIDDEN + head * HDIM + i + 32];
        float rk0 = k0 * c - k1 * s;
        float rk1 = k1 * c + k0 * s;
        fsplit(rk0, hi, lo); khi[obase] = hi;      klo[obase] = lo;
        fsplit(rk1, hi, lo); khi[obase + 32] = hi; klo[obase + 32] = lo;
    }
    size_t a0 = (size_t)row * VFF + HIDDEN;
    for (int idx = threadIdx.x; idx < 4096; idx += 256) {
        float v = hr[3 * HIDDEN + idx];
        float g = 0.5f * v * (1.0f + erff(v * 0.70710678118654752f));
        __nv_bfloat16 hi, lo;
        fsplit(g, hi, lo);
        a2hi[a0 + idx] = hi; a2lo[a0 + idx] = lo;
    }
}

// ---------------------------------------------------------------------------
// V transpose+split
// ---------------------------------------------------------------------------
__global__ __launch_bounds__(256)
void vsplit_kernel(const float* __restrict__ h,
                   __nv_bfloat16* __restrict__ vthi, __nv_bfloat16* __restrict__ vtlo) {
    __shared__ float sm[64][65];
    int l0 = blockIdx.x * 64;
    int bh = blockIdx.y;
    int b = bh >> 4, head = bh & 15;
    int tid = threadIdx.x;

    for (int idx = tid; idx < 64 * 64; idx += 256) {
        int r = idx >> 6, d = idx & 63;
        sm[r][d] = h[(size_t)(b * LSEQ + l0 + r) * QKVFF + 2 * HIDDEN + head * HDIM + d];
    }
    __syncthreads();
    for (int idx = tid; idx < 64 * 64; idx += 256) {
        int d = idx >> 6, c = idx & 63;
        float v = sm[c][d];
        __nv_bfloat16 hi, lo;
        fsplit(v, hi, lo);
        size_t o = ((size_t)bh * HDIM + d) * LSEQ + l0 + c;
        vthi[o] = hi; vtlo[o] = lo;
    }
}

// ---------------------------------------------------------------------------
// 4) Flash attention on mma.sync (heavy tiles launched first)
// ---------------------------------------------------------------------------
#define ASTRIDE  144
#define SQ_BYTES (128 * ASTRIDE)
#define KV_MAT   (64 * ASTRIDE)
#define KV_STAGE (4 * KV_MAT)
#define ATT_SMEM (2 * SQ_BYTES + 2 * KV_STAGE)

__global__ __launch_bounds__(256)
void attn_mma(const __nv_bfloat16* __restrict__ Qhi, const __nv_bfloat16* __restrict__ Qlo,
              const __nv_bfloat16* __restrict__ Khi, const __nv_bfloat16* __restrict__ Klo,
              const __nv_bfloat16* __restrict__ Vthi, const __nv_bfloat16* __restrict__ Vtlo,
              __nv_bfloat16* __restrict__ a2hi, __nv_bfloat16* __restrict__ a2lo) {
    extern __shared__ char dsm[];
    uint32_t sb  = smem_u32(dsm);
    uint32_t sQh = sb, sQl = sb + SQ_BYTES;
    uint32_t sKV = sb + 2 * SQ_BYTES;

    int tid = threadIdx.x, warp = tid >> 5, lane = tid & 31;
    int q0 = (gridDim.x - 1 - blockIdx.x) * 128;   // heavy tiles first
    int bh = blockIdx.y;
    int head = bh & 15;
    size_t kvbase = (size_t)bh * LSEQ * HDIM;
    size_t vtbase = (size_t)bh * HDIM * LSEQ;

    for (int t = 0; t < 8; t++) {
        int idx = t * 256 + tid;
        int mat = idx >> 10;
        int r   = (idx >> 3) & 127;
        int cg  = idx & 7;
        const __nv_bfloat16* src = (mat ? Qlo : Qhi) + kvbase + (size_t)(q0 + r) * HDIM + cg * 8;
        uint32_t dst = (mat ? sQl : sQh) + r * ASTRIDE + cg * 16;
        CP_ASYNC16(dst, src);
    }
    CP_COMMIT();

    int NT = (q0 >> 6) + 2;

    auto load_kv = [&](int s, int jt) {
        int kv0 = jt * 64;
        uint32_t stage = sKV + s * KV_STAGE;
#pragma unroll
        for (int t = 0; t < 8; t++) {
            int idx = t * 256 + tid;
            int mat = idx >> 9;
            int r   = (idx >> 3) & 63;
            int cg  = idx & 7;
            const __nv_bfloat16* src;
            if (mat == 0)      src = Khi  + kvbase + (size_t)(kv0 + r) * HDIM + cg * 8;
            else if (mat == 1) src = Klo  + kvbase + (size_t)(kv0 + r) * HDIM + cg * 8;
            else if (mat == 2) src = Vthi + vtbase + (size_t)r * LSEQ + kv0 + cg * 8;
            else               src = Vtlo + vtbase + (size_t)r * LSEQ + kv0 + cg * 8;
            uint32_t dst = stage + mat * KV_MAT + r * ASTRIDE + cg * 16;
            CP_ASYNC16(dst, src);
        }
    };

    load_kv(0, 0);
    CP_COMMIT();
    CP_WAIT1();
    __syncthreads();

    uint32_t qh[4][4], ql[4][4];
    {
        int arow = warp * 16 + (lane & 15);
        int acolb = ((lane >> 4) << 3) * 2;
#pragma unroll
        for (int k16 = 0; k16 < 4; k16++) {
            uint32_t off = (uint32_t)(arow * ASTRIDE + k16 * 32 + acolb);
            LDM_X4(qh[k16][0], qh[k16][1], qh[k16][2], qh[k16][3], sQh + off);
            LDM_X4(ql[k16][0], ql[k16][1], ql[k16][2], ql[k16][3], sQl + off);
        }
    }

    float Oacc[8][4];
#pragma unroll
    for (int j = 0; j < 8; j++)
#pragma unroll
        for (int q = 0; q < 4; q++) Oacc[j][q] = 0.f;
    float m[2] = {-INFINITY, -INFINITY};
    float lsum[2] = {0.f, 0.f};

    int qw_base = q0 + warp * 16;
    int r0 = lane >> 2;
    int brow_l = (lane & 7) + ((lane & 16) >> 1);
    int bcolb  = (((lane >> 3) & 1) * 8) * 2;

    for (int jt = 0; jt < NT; jt++) {
        if (jt + 1 < NT) load_kv((jt + 1) & 1, jt + 1);
        CP_COMMIT();
        if (jt + 1 < NT) CP_WAIT1(); else CP_WAIT0();
        __syncthreads();

        int kv0 = jt * 64;
        bool skip = (kv0 > qw_base + 15);
        if (!skip) {
            uint32_t st  = sKV + (jt & 1) * KV_STAGE;
            uint32_t sKh = st, sKl = st + KV_MAT;
            uint32_t sVh = st + 2 * KV_MAT, sVl = st + 3 * KV_MAT;

            float S[8][4];
#pragma unroll
            for (int j = 0; j < 8; j++)
#pragma unroll
                for (int q = 0; q < 4; q++) S[j][q] = 0.f;

#pragma unroll
            for (int k16 = 0; k16 < 4; k16++) {
#pragma unroll
                for (int ng = 0; ng < 4; ng++) {
                    uint32_t boff = (uint32_t)((ng * 16 + brow_l) * ASTRIDE + k16 * 32 + bcolb);
                    uint32_t kh[4], kl[4];
                    LDM_X4(kh[0], kh[1], kh[2], kh[3], sKh + boff);
                    LDM_X4(kl[0], kl[1], kl[2], kl[3], sKl + boff);
#pragma unroll
                    for (int tt = 0; tt < 2; tt++) {
                        int j = 2 * ng + tt;
                        mma_bf16(S[j], qh[k16], &kh[2 * tt]);
                        mma_bf16(S[j], ql[k16], &kh[2 * tt]);
                        mma_bf16(S[j], qh[k16], &kl[2 * tt]);
                    }
                }
            }

            if (kv0 + 63 > qw_base) {
#pragma unroll
                for (int hh = 0; hh < 2; hh++) {
                    int qrow = qw_base + r0 + hh * 8;
#pragma unroll
                    for (int j = 0; j < 8; j++) {
                        int kvc = kv0 + j * 8 + (lane & 3) * 2;
                        if (kvc > qrow)     S[j][2 * hh]     = -1e30f;
                        if (kvc + 1 > qrow) S[j][2 * hh + 1] = -1e30f;
                    }
                }
            }

#pragma unroll
            for (int hh = 0; hh < 2; hh++) {
                float rm = -1e30f;
#pragma unroll
                for (int j = 0; j < 8; j++)
                    rm = fmaxf(rm, fmaxf(S[j][2 * hh], S[j][2 * hh + 1]));
                rm = fmaxf(rm, __shfl_xor_sync(0xffffffffu, rm, 1));
                rm = fmaxf(rm, __shfl_xor_sync(0xffffffffu, rm, 2));
                float mnew = fmaxf(m[hh], rm);
                float corr = __expf(m[hh] - mnew);
                m[hh] = mnew;
                float rs = 0.f;
#pragma unroll
                for (int j = 0; j < 8; j++) {
                    float e0 = __expf(S[j][2 * hh]     - mnew);
                    float e1 = __expf(S[j][2 * hh + 1] - mnew);
                    S[j][2 * hh] = e0; S[j][2 * hh + 1] = e1;
                    rs += e0 + e1;
                }
                rs += __shfl_xor_sync(0xffffffffu, rs, 1);
                rs += __shfl_xor_sync(0xffffffffu, rs, 2);
                lsum[hh] = lsum[hh] * corr + rs;
#pragma unroll
                for (int j = 0; j < 8; j++) {
                    Oacc[j][2 * hh]     *= corr;
                    Oacc[j][2 * hh + 1] *= corr;
                }
            }

#pragma unroll
            for (int k16 = 0; k16 < 4; k16++) {
                uint32_t ph[4], pl[4];
#pragma unroll
                for (int half = 0; half < 2; half++) {
                    int j = 2 * k16 + half;
#pragma unroll
                    for (int hh = 0; hh < 2; hh++) {
                        float v0 = S[j][2 * hh], v1 = S[j][2 * hh + 1];
                        float h0 = __bfloat162float(__float2bfloat16(v0));
                        float h1 = __bfloat162float(__float2bfloat16(v1));
                        ph[half * 2 + hh] = pack_bf16x2(h0, h1);
                        pl[half * 2 + hh] = pack_bf16x2(v0 - h0, v1 - h1);
                    }
                }
#pragma unroll
                for (int ng = 0; ng < 4; ng++) {
                    uint32_t boff = (uint32_t)((ng * 16 + brow_l) * ASTRIDE + k16 * 32 + bcolb);
                    uint32_t vh[4], vl[4];
                    LDM_X4(vh[0], vh[1], vh[2], vh[3], sVh + boff);
                    LDM_X4(vl[0], vl[1], vl[2], vl[3], sVl + boff);
#pragma unroll
                    for (int tt = 0; tt < 2; tt++) {
                        int j = 2 * ng + tt;
                        mma_bf16(Oacc[j], ph, &vh[2 * tt]);
                        mma_bf16(Oacc[j], pl, &vh[2 * tt]);
                        mma_bf16(Oacc[j], ph, &vl[2 * tt]);
                    }
                }
            }
        }
        __syncthreads();
    }

#pragma unroll
    for (int hh = 0; hh < 2; hh++) {
        float inv = 1.0f / lsum[hh];
        int row = qw_base + r0 + hh * 8;
        int qrow_global = (bh >> 4) * LSEQ + (row & (LSEQ - 1));
        size_t obase = (size_t)qrow_global * VFF + head * HDIM + (lane & 3) * 2;
#pragma unroll
        for (int j = 0; j < 8; j++) {
            float v0 = Oacc[j][2 * hh] * inv;
            float v1 = Oacc[j][2 * hh + 1] * inv;
            __nv_bfloat16 h0, l0, h1, l1;
            fsplit(v0, h0, l0); fsplit(v1, h1, l1);
            __nv_bfloat162 phv; phv.x = h0; phv.y = h1;
            __nv_bfloat162 plv; plv.x = l0; plv.y = l1;
            *(__nv_bfloat162*)(a2hi + obase + j * 8) = phv;
            *(__nv_bfloat162*)(a2lo + obase + j * 8) = plv;
        }
    }
}

// ---------------------------------------------------------------------------
// launch
// ---------------------------------------------------------------------------
extern "C" void kernel_launch(void* const* d_in, const int* in_sizes, int n_in,
                              void* d_out, int out_size) {
    const float* x     = (const float*)d_in[0];
    const float* ln_w  = (const float*)d_in[1];
    const float* ln_b  = (const float*)d_in[2];
    const float* W_in  = (const float*)d_in[3];
    const float* W_out = (const float*)d_in[4];
    float* out = (float*)d_out;

    float* h;   cudaGetSymbolAddress((void**)&h, g_h);
    __nv_bfloat16 *a1hi, *a1lo, *b1hi, *b1lo, *a2hi, *a2lo, *b2hi, *b2lo;
    __nv_bfloat16 *qhi, *qlo, *khi, *klo, *vthi, *vtlo;
    cudaGetSymbolAddress((void**)&a1hi, g_A1hi);
    cudaGetSymbolAddress((void**)&a1lo, g_A1lo);
    cudaGetSymbolAddress((void**)&b1hi, g_B1hi);
    cudaGetSymbolAddress((void**)&b1lo, g_B1lo);
    cudaGetSymbolAddress((void**)&a2hi, g_A2hi);
    cudaGetSymbolAddress((void**)&a2lo, g_A2lo);
    cudaGetSymbolAddress((void**)&b2hi, g_B2hi);
    cudaGetSymbolAddress((void**)&b2lo, g_B2lo);
    cudaGetSymbolAddress((void**)&qhi,  g_Qhi);
    cudaGetSymbolAddress((void**)&qlo,  g_Qlo);
    cudaGetSymbolAddress((void**)&khi,  g_Khi);
    cudaGetSymbolAddress((void**)&klo,  g_Klo);
    cudaGetSymbolAddress((void**)&vthi, g_Vthi);
    cudaGetSymbolAddress((void**)&vtlo, g_Vtlo);

    cudaFuncSetAttribute(gemm_mma, cudaFuncAttributeMaxDynamicSharedMemorySize, GSMEM);
    cudaFuncSetAttribute(attn_mma, cudaFuncAttributeMaxDynamicSharedMemorySize, ATT_SMEM);

    convw_kernel<<<dim3(QKVFF / 32, HIDDEN / 32), 256>>>(W_in,  b1hi, b1lo, HIDDEN, QKVFF);
    convw_kernel<<<dim3(HIDDEN / 32, VFF / 32),   256>>>(W_out, b2hi, b2lo, VFF,    HIDDEN);

    ln_kernel<<<R_ROWS, 256>>>(x, ln_w, ln_b, a1hi, a1lo);

    gemm_mma<<<dim3(QKVFF / 128, R_ROWS / 128), 256, GSMEM>>>(
        a1hi, a1lo, b1hi, b1lo, h, HIDDEN, QKVFF);

    rope_gelu_kernel<<<R_ROWS, 256>>>(h, qhi, qlo, khi, klo, a2hi, a2lo);
    vsplit_kernel<<<dim3(LSEQ / 64, 32), 256>>>(h, vthi, vtlo);

    attn_mma<<<dim3(LSEQ / 128, 32), 256, ATT_SMEM>>>(
        qhi, qlo, khi, klo, vthi, vtlo, a2hi, a2lo);

    gemm_mma<<<dim3(HIDDEN / 128, R_ROWS / 128), 256, GSMEM>>>(
        a2hi, a2lo, b2hi, b2lo, out, VFF, HIDDEN);
}

// round 10
// speedup vs baseline: 1.0018x; 1.0018x over previous
#include <cuda_runtime.h>
#include <cuda_bf16.h>
#include <math.h>
#include <stdint.h>

// ---------------------------------------------------------------------------
#define R_ROWS   4096
#define HIDDEN   1024
#define QKVFF    7168
#define VFF      5120
#define LSEQ     2048
#define NHEADS   16
#define HDIM     64
#define LN_EPS   1e-5f

// ---------------------------------------------------------------------------
// Device scratch
// ---------------------------------------------------------------------------
__device__ float g_h[(size_t)R_ROWS * QKVFF];
__device__ __nv_bfloat16 g_A1hi[(size_t)R_ROWS * HIDDEN];
__device__ __nv_bfloat16 g_A1lo[(size_t)R_ROWS * HIDDEN];
__device__ __nv_bfloat16 g_B1hi[(size_t)QKVFF * HIDDEN];
__device__ __nv_bfloat16 g_B1lo[(size_t)QKVFF * HIDDEN];
__device__ __nv_bfloat16 g_A2hi[(size_t)R_ROWS * VFF];
__device__ __nv_bfloat16 g_A2lo[(size_t)R_ROWS * VFF];
__device__ __nv_bfloat16 g_B2hi[(size_t)HIDDEN * VFF];
__device__ __nv_bfloat16 g_B2lo[(size_t)HIDDEN * VFF];
__device__ __nv_bfloat16 g_Qhi[(size_t)32 * LSEQ * HDIM];
__device__ __nv_bfloat16 g_Qlo[(size_t)32 * LSEQ * HDIM];
__device__ __nv_bfloat16 g_Khi[(size_t)32 * LSEQ * HDIM];
__device__ __nv_bfloat16 g_Klo[(size_t)32 * LSEQ * HDIM];
__device__ __nv_bfloat16 g_Vthi[(size_t)32 * HDIM * LSEQ];
__device__ __nv_bfloat16 g_Vtlo[(size_t)32 * HDIM * LSEQ];

// ---------------------------------------------------------------------------
// helpers
// ---------------------------------------------------------------------------
static __device__ __forceinline__ uint32_t smem_u32(const void* p) {
    uint32_t a;
    asm("{ .reg .u64 t; cvta.to.shared.u64 t, %1; cvt.u32.u64 %0, t; }"
        : "=r"(a) : "l"(p));
    return a;
}
static __device__ __forceinline__ void fsplit(float v, __nv_bfloat16& hi, __nv_bfloat16& lo) {
    hi = __float2bfloat16(v);
    lo = __float2bfloat16(v - __bfloat162float(hi));
}
static __device__ __forceinline__ uint32_t pack_bf16x2(float lo, float hi) {
    uint32_t r;
    asm("cvt.rn.bf16x2.f32 %0, %1, %2;" : "=r"(r) : "f"(hi), "f"(lo));
    return r;
}

#define CP_ASYNC16(dst, src) \
    asm volatile("cp.async.cg.shared.global [%0], [%1], 16;" :: "r"(dst), "l"(src) : "memory")
#define CP_COMMIT() asm volatile("cp.async.commit_group;" ::: "memory")
#define CP_WAIT1()  asm volatile("cp.async.wait_group 1;" ::: "memory")
#define CP_WAIT0()  asm volatile("cp.async.wait_group 0;" ::: "memory")

#define LDM_X4(r0, r1, r2, r3, addr)                                          \
    asm volatile("ldmatrix.sync.aligned.m8n8.x4.shared.b16 {%0,%1,%2,%3}, [%4];" \
                 : "=r"(r0), "=r"(r1), "=r"(r2), "=r"(r3) : "r"(addr))

static __device__ __forceinline__ void mma_bf16(float* d, const uint32_t* a,
                                                const uint32_t* b) {
    asm volatile(
        "mma.sync.aligned.m16n8k16.row.col.f32.bf16.bf16.f32 "
        "{%0,%1,%2,%3}, {%4,%5,%6,%7}, {%8,%9}, {%0,%1,%2,%3};"
        : "+f"(d[0]), "+f"(d[1]), "+f"(d[2]), "+f"(d[3])
        : "r"(a[0]), "r"(a[1]), "r"(a[2]), "r"(a[3]), "r"(b[0]), "r"(b[1]));
}

// ---------------------------------------------------------------------------
// 1) LayerNorm -> bf16 hi/lo operand A1
// ---------------------------------------------------------------------------
__global__ __launch_bounds__(256)
void ln_kernel(const float* __restrict__ x, const float* __restrict__ w,
               const float* __restrict__ b,
               __nv_bfloat16* __restrict__ a_hi, __nv_bfloat16* __restrict__ a_lo) {
    int row = blockIdx.x;
    const float* xr = x + (size_t)row * HIDDEN;
    int tid = threadIdx.x;

    float4 v = *(const float4*)(xr + tid * 4);
    float s  = v.x + v.y + v.z + v.w;
    float s2 = v.x * v.x + v.y * v.y + v.z * v.z + v.w * v.w;
    for (int off = 16; off >= 1; off >>= 1) {
        s  += __shfl_xor_sync(0xffffffffu, s,  off);
        s2 += __shfl_xor_sync(0xffffffffu, s2, off);
    }
    __shared__ float ws[8], ws2[8];
    int wid = tid >> 5, lid = tid & 31;
    if (lid == 0) { ws[wid] = s; ws2[wid] = s2; }
    __syncthreads();
    if (wid == 0) {
        float a  = (lid < 8) ? ws[lid]  : 0.f;
        float a2 = (lid < 8) ? ws2[lid] : 0.f;
        for (int off = 4; off >= 1; off >>= 1) {
            a  += __shfl_xor_sync(0xffffffffu, a,  off);
            a2 += __shfl_xor_sync(0xffffffffu, a2, off);
        }
        if (lid == 0) { ws[0] = a; ws2[0] = a2; }
    }
    __syncthreads();
    float mu  = ws[0] * (1.0f / HIDDEN);
    float var = ws2[0] * (1.0f / HIDDEN) - mu * mu;
    float rsig = rsqrtf(var + LN_EPS);

    float4 wv = *(const float4*)(w + tid * 4);
    float4 bv = *(const float4*)(b + tid * 4);
    float o0 = (v.x - mu) * rsig * wv.x + bv.x;
    float o1 = (v.y - mu) * rsig * wv.y + bv.y;
    float o2 = (v.z - mu) * rsig * wv.z + bv.z;
    float o3 = (v.w - mu) * rsig * wv.w + bv.w;

    size_t base = (size_t)row * HIDDEN + tid * 4;
    __nv_bfloat16 h0, l0, h1, l1, h2, l2, h3, l3;
    fsplit(o0, h0, l0); fsplit(o1, h1, l1); fsplit(o2, h2, l2); fsplit(o3, h3, l3);
    a_hi[base + 0] = h0; a_hi[base + 1] = h1; a_hi[base + 2] = h2; a_hi[base + 3] = h3;
    a_lo[base + 0] = l0; a_lo[base + 1] = l1; a_lo[base + 2] = l2; a_lo[base + 3] = l3;
}

// ---------------------------------------------------------------------------
// Weight transpose + hi/lo split
// ---------------------------------------------------------------------------
__global__ __launch_bounds__(256)
void convw_kernel(const float* __restrict__ W,
                  __nv_bfloat16* __restrict__ bhi, __nv_bfloat16* __restrict__ blo,
                  int K, int N) {
    __shared__ float t[32][33];
    int n0 = blockIdx.x * 32, k0 = blockIdx.y * 32;
    int tx = threadIdx.x & 31, ty = threadIdx.x >> 5;
    for (int r = ty; r < 32; r += 8)
        t[r][tx] = W[(size_t)(k0 + r) * N + n0 + tx];
    __syncthreads();
    for (int r = ty; r < 32; r += 8) {
        float v = t[tx][r];
        __nv_bfloat16 hi, lo;
        fsplit(v, hi, lo);
        size_t o = (size_t)(n0 + r) * K + k0 + tx;
        bhi[o] = hi; blo[o] = lo;
    }
}

// ---------------------------------------------------------------------------
// mma.sync GEMM — now __launch_bounds__(256, 2): cap 128 regs so 2 CTAs/SM.
// ---------------------------------------------------------------------------
#define GSTAGE   40960
#define GSMEM    (2 * GSTAGE)
#define GSTRIDE  80

__global__ __launch_bounds__(256, 2)
void gemm_mma(const __nv_bfloat16* __restrict__ Ahi, const __nv_bfloat16* __restrict__ Alo,
              const __nv_bfloat16* __restrict__ Bhi, const __nv_bfloat16* __restrict__ Blo,
              float* __restrict__ C, int K, int ldc) {
    extern __shared__ char dsm[];
    uint32_t sb = smem_u32(dsm);

    int tid = threadIdx.x, warp = tid >> 5, lane = tid & 31;
    int m0 = blockIdx.y * 128, n0 = blockIdx.x * 128;
    int warp_m = (warp & 3) * 32, warp_n = (warp >> 2) * 64;

    const __nv_bfloat16* gmat[4] = {Ahi, Alo, Bhi, Blo};

    auto load_stage = [&](int s, int kt) {
        uint32_t stage = sb + s * GSTAGE;
#pragma unroll
        for (int t = 0; t < 8; t++) {
            int idx = t * 256 + tid;
            int mat = idx >> 9;
            int r   = (idx >> 2) & 127;
            int cg  = idx & 3;
            int row0 = (mat < 2) ? m0 : n0;
            const __nv_bfloat16* src = gmat[mat] + (size_t)(row0 + r) * K + kt + cg * 8;
            uint32_t dst = stage + mat * 10240 + r * GSTRIDE + cg * 16;
            CP_ASYNC16(dst, src);
        }
    };

    float acc[2][8][4];
#pragma unroll
    for (int i = 0; i < 2; i++)
#pragma unroll
        for (int j = 0; j < 8; j++)
#pragma unroll
            for (int q = 0; q < 4; q++) acc[i][j][q] = 0.f;

    int NC = K >> 5;
    load_stage(0, 0);
    CP_COMMIT();

    for (int c = 0; c < NC; c++) {
        if (c + 1 < NC) load_stage((c + 1) & 1, (c + 1) * 32);
        CP_COMMIT();
        if (c + 1 < NC) CP_WAIT1(); else CP_WAIT0();
        __syncthreads();

        uint32_t st  = sb + (c & 1) * GSTAGE;
        uint32_t sAh = st, sAl = st + 10240, sBh = st + 20480, sBl = st + 30720;

#pragma unroll
        for (int k16 = 0; k16 < 2; k16++) {
            int k0 = k16 * 16;
            uint32_t ah[2][4], al[2][4];
            {
                int arow = warp_m + (lane & 15);
                int acol = k0 + ((lane >> 4) << 3);
                uint32_t off0 = (uint32_t)(arow * GSTRIDE + acol * 2);
                uint32_t off1 = off0 + 16 * GSTRIDE;
                LDM_X4(ah[0][0], ah[0][1], ah[0][2], ah[0][3], sAh + off0);
                LDM_X4(ah[1][0], ah[1][1], ah[1][2], ah[1][3], sAh + off1);
                LDM_X4(al[0][0], al[0][1], al[0][2], al[0][3], sAl + off0);
                LDM_X4(al[1][0], al[1][1], al[1][2], al[1][3], sAl + off1);
            }
            int brow_l = (lane & 7) + ((lane & 16) >> 1);
            int bcol   = k0 + ((lane >> 3) & 1) * 8;
#pragma unroll
            for (int ng = 0; ng < 4; ng++) {
                uint32_t boff = (uint32_t)((warp_n + ng * 16 + brow_l) * GSTRIDE + bcol * 2);
                uint32_t bh[4], bl[4];
                LDM_X4(bh[0], bh[1], bh[2], bh[3], sBh + boff);
                LDM_X4(bl[0], bl[1], bl[2], bl[3], sBl + boff);
#pragma unroll
                for (int mt = 0; mt < 2; mt++)
#pragma unroll
                    for (int tt = 0; tt < 2; tt++) {
                        int nt = 2 * ng + tt;
                        mma_bf16(acc[mt][nt], ah[mt], &bh[2 * tt]);
                        mma_bf16(acc[mt][nt], al[mt], &bh[2 * tt]);
                        mma_bf16(acc[mt][nt], ah[mt], &bl[2 * tt]);
                    }
            }
        }
        __syncthreads();
    }

    int rbase = m0 + warp_m + (lane >> 2);
    int cbase = n0 + warp_n + (lane & 3) * 2;
#pragma unroll
    for (int mt = 0; mt < 2; mt++)
#pragma unroll
        for (int nt = 0; nt < 8; nt++) {
            int r = rbase + mt * 16;
            int cc = cbase + nt * 8;
            *(float2*)(C + (size_t)r * ldc + cc) =
                make_float2(acc[mt][nt][0], acc[mt][nt][1]);
            *(float2*)(C + (size_t)(r + 8) * ldc + cc) =
                make_float2(acc[mt][nt][2], acc[mt][nt][3]);
        }
}

// ---------------------------------------------------------------------------
// 3) RoPE -> split q/k; GELU(ff) -> A2 cols [1024, 5120)
// ---------------------------------------------------------------------------
__global__ __launch_bounds__(256)
void rope_gelu_kernel(const float* __restrict__ h,
                      __nv_bfloat16* __restrict__ qhi, __nv_bfloat16* __restrict__ qlo,
                      __nv_bfloat16* __restrict__ khi, __nv_bfloat16* __restrict__ klo,
                      __nv_bfloat16* __restrict__ a2hi, __nv_bfloat16* __restrict__ a2lo) {
    int row = blockIdx.x;
    int b = row >> 11, l = row & (LSEQ - 1);
    const float* hr = h + (size_t)row * QKVFF;

    for (int idx = threadIdx.x; idx < NHEADS * 32; idx += 256) {
        int head = idx >> 5, i = idx & 31;
        float invf = (float)exp(-(double)i / 32.0 * log(10000.0));
        float ang = (float)l * invf;
        float c = cosf(ang), s = sinf(ang);
        size_t obase = ((size_t)(b * NHEADS + head) * LSEQ + l) * HDIM + i;

        float q0 = hr[head * HDIM + i], q1 = hr[head * HDIM + i + 32];
        float rq0 = (q0 * c - q1 * s) * 0.125f;
        float rq1 = (q1 * c + q0 * s) * 0.125f;
        __nv_bfloat16 hi, lo;
        fsplit(rq0, hi, lo); qhi[obase] = hi;      qlo[obase] = lo;
        fsplit(rq1, hi, lo); qhi[obase + 32] = hi; qlo[obase + 32] = lo;

        float k0 = hr[HIDDEN + head * HDIM + i], k1 = hr[HIDDEN + head * HDIM + i + 32];
        float rk0 = k0 * c - k1 * s;
        float rk1 = k1 * c + k0 * s;
        fsplit(rk0, hi, lo); khi[obase] = hi;      klo[obase] = lo;
        fsplit(rk1, hi, lo); khi[obase + 32] = hi; klo[obase + 32] = lo;
    }
    size_t a0 = (size_t)row * VFF + HIDDEN;
    for (int idx = threadIdx.x; idx < 4096; idx += 256) {
        float v = hr[3 * HIDDEN + idx];
        float g = 0.5f * v * (1.0f + erff(v * 0.70710678118654752f));
        __nv_bfloat16 hi, lo;
        fsplit(g, hi, lo);
        a2hi[a0 + idx] = hi; a2lo[a0 + idx] = lo;
    }
}

// ---------------------------------------------------------------------------
// V transpose+split
// ---------------------------------------------------------------------------
__global__ __launch_bounds__(256)
void vsplit_kernel(const float* __restrict__ h,
                   __nv_bfloat16* __restrict__ vthi, __nv_bfloat16* __restrict__ vtlo) {
    __shared__ float sm[64][65];
    int l0 = blockIdx.x * 64;
    int bh = blockIdx.y;
    int b = bh >> 4, head = bh & 15;
    int tid = threadIdx.x;

    for (int idx = tid; idx < 64 * 64; idx += 256) {
        int r = idx >> 6, d = idx & 63;
        sm[r][d] = h[(size_t)(b * LSEQ + l0 + r) * QKVFF + 2 * HIDDEN + head * HDIM + d];
    }
    __syncthreads();
    for (int idx = tid; idx < 64 * 64; idx += 256) {
        int d = idx >> 6, c = idx & 63;
        float v = sm[c][d];
        __nv_bfloat16 hi, lo;
        fsplit(v, hi, lo);
        size_t o = ((size_t)bh * HDIM + d) * LSEQ + l0 + c;
        vthi[o] = hi; vtlo[o] = lo;
    }
}

// ---------------------------------------------------------------------------
// 4) Flash attention on mma.sync (heavy tiles launched first)
// ---------------------------------------------------------------------------
#define ASTRIDE  144
#define SQ_BYTES (128 * ASTRIDE)
#define KV_MAT   (64 * ASTRIDE)
#define KV_STAGE (4 * KV_MAT)
#define ATT_SMEM (2 * SQ_BYTES + 2 * KV_STAGE)

__global__ __launch_bounds__(256)
void attn_mma(const __nv_bfloat16* __restrict__ Qhi, const __nv_bfloat16* __restrict__ Qlo,
              const __nv_bfloat16* __restrict__ Khi, const __nv_bfloat16* __restrict__ Klo,
              const __nv_bfloat16* __restrict__ Vthi, const __nv_bfloat16* __restrict__ Vtlo,
              __nv_bfloat16* __restrict__ a2hi, __nv_bfloat16* __restrict__ a2lo) {
    extern __shared__ char dsm[];
    uint32_t sb  = smem_u32(dsm);
    uint32_t sQh = sb, sQl = sb + SQ_BYTES;
    uint32_t sKV = sb + 2 * SQ_BYTES;

    int tid = threadIdx.x, warp = tid >> 5, lane = tid & 31;
    int q0 = (gridDim.x - 1 - blockIdx.x) * 128;   // heavy tiles first
    int bh = blockIdx.y;
    int head = bh & 15;
    size_t kvbase = (size_t)bh * LSEQ * HDIM;
    size_t vtbase = (size_t)bh * HDIM * LSEQ;

    for (int t = 0; t < 8; t++) {
        int idx = t * 256 + tid;
        int mat = idx >> 10;
        int r   = (idx >> 3) & 127;
        int cg  = idx & 7;
        const __nv_bfloat16* src = (mat ? Qlo : Qhi) + kvbase + (size_t)(q0 + r) * HDIM + cg * 8;
        uint32_t dst = (mat ? sQl : sQh) + r * ASTRIDE + cg * 16;
        CP_ASYNC16(dst, src);
    }
    CP_COMMIT();

    int NT = (q0 >> 6) + 2;

    auto load_kv = [&](int s, int jt) {
        int kv0 = jt * 64;
        uint32_t stage = sKV + s * KV_STAGE;
#pragma unroll
        for (int t = 0; t < 8; t++) {
            int idx = t * 256 + tid;
            int mat = idx >> 9;
            int r   = (idx >> 3) & 63;
            int cg  = idx & 7;
            const __nv_bfloat16* src;
            if (mat == 0)      src = Khi  + kvbase + (size_t)(kv0 + r) * HDIM + cg * 8;
            else if (mat == 1) src = Klo  + kvbase + (size_t)(kv0 + r) * HDIM + cg * 8;
            else if (mat == 2) src = Vthi + vtbase + (size_t)r * LSEQ + kv0 + cg * 8;
            else               src = Vtlo + vtbase + (size_t)r * LSEQ + kv0 + cg * 8;
            uint32_t dst = stage + mat * KV_MAT + r * ASTRIDE + cg * 16;
            CP_ASYNC16(dst, src);
        }
    };

    load_kv(0, 0);
    CP_COMMIT();
    CP_WAIT1();
    __syncthreads();

    uint32_t qh[4][4], ql[4][4];
    {
        int arow = warp * 16 + (lane & 15);
        int acolb = ((lane >> 4) << 3) * 2;
#pragma unroll
        for (int k16 = 0; k16 < 4; k16++) {
            uint32_t off = (uint32_t)(arow * ASTRIDE + k16 * 32 + acolb);
            LDM_X4(qh[k16][0], qh[k16][1], qh[k16][2], qh[k16][3], sQh + off);
            LDM_X4(ql[k16][0], ql[k16][1], ql[k16][2], ql[k16][3], sQl + off);
        }
    }

    float Oacc[8][4];
#pragma unroll
    for (int j = 0; j < 8; j++)
#pragma unroll
        for (int q = 0; q < 4; q++) Oacc[j][q] = 0.f;
    float m[2] = {-INFINITY, -INFINITY};
    float lsum[2] = {0.f, 0.f};

    int qw_base = q0 + warp * 16;
    int r0 = lane >> 2;
    int brow_l = (lane & 7) + ((lane & 16) >> 1);
    int bcolb  = (((lane >> 3) & 1) * 8) * 2;

    for (int jt = 0; jt < NT; jt++) {
        if (jt + 1 < NT) load_kv((jt + 1) & 1, jt + 1);
        CP_COMMIT();
        if (jt + 1 < NT) CP_WAIT1(); else CP_WAIT0();
        __syncthreads();

        int kv0 = jt * 64;
        bool skip = (kv0 > qw_base + 15);
        if (!skip) {
            uint32_t st  = sKV + (jt & 1) * KV_STAGE;
            uint32_t sKh = st, sKl = st + KV_MAT;
            uint32_t sVh = st + 2 * KV_MAT, sVl = st + 3 * KV_MAT;

            float S[8][4];
#pragma unroll
            for (int j = 0; j < 8; j++)
#pragma unroll
                for (int q = 0; q < 4; q++) S[j][q] = 0.f;

#pragma unroll
            for (int k16 = 0; k16 < 4; k16++) {
#pragma unroll
                for (int ng = 0; ng < 4; ng++) {
                    uint32_t boff = (uint32_t)((ng * 16 + brow_l) * ASTRIDE + k16 * 32 + bcolb);
                    uint32_t kh[4], kl[4];
                    LDM_X4(kh[0], kh[1], kh[2], kh[3], sKh + boff);
                    LDM_X4(kl[0], kl[1], kl[2], kl[3], sKl + boff);
#pragma unroll
                    for (int tt = 0; tt < 2; tt++) {
                        int j = 2 * ng + tt;
                        mma_bf16(S[j], qh[k16], &kh[2 * tt]);
                        mma_bf16(S[j], ql[k16], &kh[2 * tt]);
                        mma_bf16(S[j], qh[k16], &kl[2 * tt]);
                    }
                }
            }

            if (kv0 + 63 > qw_base) {
#pragma unroll
                for (int hh = 0; hh < 2; hh++) {
                    int qrow = qw_base + r0 + hh * 8;
#pragma unroll
                    for (int j = 0; j < 8; j++) {
                        int kvc = kv0 + j * 8 + (lane & 3) * 2;
                        if (kvc > qrow)     S[j][2 * hh]     = -1e30f;
                        if (kvc + 1 > qrow) S[j][2 * hh + 1] = -1e30f;
                    }
                }
            }

#pragma unroll
            for (int hh = 0; hh < 2; hh++) {
                float rm = -1e30f;
#pragma unroll
                for (int j = 0; j < 8; j++)
                    rm = fmaxf(rm, fmaxf(S[j][2 * hh], S[j][2 * hh + 1]));
                rm = fmaxf(rm, __shfl_xor_sync(0xffffffffu, rm, 1));
                rm = fmaxf(rm, __shfl_xor_sync(0xffffffffu, rm, 2));
                float mnew = fmaxf(m[hh], rm);
                float corr = __expf(m[hh] - mnew);
                m[hh] = mnew;
                float rs = 0.f;
#pragma unroll
                for (int j = 0; j < 8; j++) {
                    float e0 = __expf(S[j][2 * hh]     - mnew);
                    float e1 = __expf(S[j][2 * hh + 1] - mnew);
                    S[j][2 * hh] = e0; S[j][2 * hh + 1] = e1;
                    rs += e0 + e1;
                }
                rs += __shfl_xor_sync(0xffffffffu, rs, 1);
                rs += __shfl_xor_sync(0xffffffffu, rs, 2);
                lsum[hh] = lsum[hh] * corr + rs;
#pragma unroll
                for (int j = 0; j < 8; j++) {
                    Oacc[j][2 * hh]     *= corr;
                    Oacc[j][2 * hh + 1] *= corr;
                }
            }

#pragma unroll
            for (int k16 = 0; k16 < 4; k16++) {
                uint32_t ph[4], pl[4];
#pragma unroll
                for (int half = 0; half < 2; half++) {
                    int j = 2 * k16 + half;
#pragma unroll
                    for (int hh = 0; hh < 2; hh++) {
                        float v0 = S[j][2 * hh], v1 = S[j][2 * hh + 1];
                        float h0 = __bfloat162float(__float2bfloat16(v0));
                        float h1 = __bfloat162float(__float2bfloat16(v1));
                        ph[half * 2 + hh] = pack_bf16x2(h0, h1);
                        pl[half * 2 + hh] = pack_bf16x2(v0 - h0, v1 - h1);
                    }
                }
#pragma unroll
                for (int ng = 0; ng < 4; ng++) {
                    uint32_t boff = (uint32_t)((ng * 16 + brow_l) * ASTRIDE + k16 * 32 + bcolb);
                    uint32_t vh[4], vl[4];
                    LDM_X4(vh[0], vh[1], vh[2], vh[3], sVh + boff);
                    LDM_X4(vl[0], vl[1], vl[2], vl[3], sVl + boff);
#pragma unroll
                    for (int tt = 0; tt < 2; tt++) {
                        int j = 2 * ng + tt;
                        mma_bf16(Oacc[j], ph, &vh[2 * tt]);
                        mma_bf16(Oacc[j], pl, &vh[2 * tt]);
                        mma_bf16(Oacc[j], ph, &vl[2 * tt]);
                    }
                }
            }
        }
        __syncthreads();
    }

#pragma unroll
    for (int hh = 0; hh < 2; hh++) {
        float inv = 1.0f / lsum[hh];
        int row = qw_base + r0 + hh * 8;
        int qrow_global = (bh >> 4) * LSEQ + (row & (LSEQ - 1));
        size_t obase = (size_t)qrow_global * VFF + head * HDIM + (lane & 3) * 2;
#pragma unroll
        for (int j = 0; j < 8; j++) {
            float v0 = Oacc[j][2 * hh] * inv;
            float v1 = Oacc[j][2 * hh + 1] * inv;
            __nv_bfloat16 h0, l0, h1, l1;
            fsplit(v0, h0, l0); fsplit(v1, h1, l1);
            __nv_bfloat162 phv; phv.x = h0; phv.y = h1;
            __nv_bfloat162 plv; plv.x = l0; plv.y = l1;
            *(__nv_bfloat162*)(a2hi + obase + j * 8) = phv;
            *(__nv_bfloat162*)(a2lo + obase + j * 8) = plv;
        }
    }
}

// ---------------------------------------------------------------------------
// launch
// ---------------------------------------------------------------------------
extern "C" void kernel_launch(void* const* d_in, const int* in_sizes, int n_in,
                              void* d_out, int out_size) {
    const float* x     = (const float*)d_in[0];
    const float* ln_w  = (const float*)d_in[1];
    const float* ln_b  = (const float*)d_in[2];
    const float* W_in  = (const float*)d_in[3];
    const float* W_out = (const float*)d_in[4];
    float* out = (float*)d_out;

    float* h;   cudaGetSymbolAddress((void**)&h, g_h);
    __nv_bfloat16 *a1hi, *a1lo, *b1hi, *b1lo, *a2hi, *a2lo, *b2hi, *b2lo;
    __nv_bfloat16 *qhi, *qlo, *khi, *klo, *vthi, *vtlo;
    cudaGetSymbolAddress((void**)&a1hi, g_A1hi);
    cudaGetSymbolAddress((void**)&a1lo, g_A1lo);
    cudaGetSymbolAddress((void**)&b1hi, g_B1hi);
    cudaGetSymbolAddress((void**)&b1lo, g_B1lo);
    cudaGetSymbolAddress((void**)&a2hi, g_A2hi);
    cudaGetSymbolAddress((void**)&a2lo, g_A2lo);
    cudaGetSymbolAddress((void**)&b2hi, g_B2hi);
    cudaGetSymbolAddress((void**)&b2lo, g_B2lo);
    cudaGetSymbolAddress((void**)&qhi,  g_Qhi);
    cudaGetSymbolAddress((void**)&qlo,  g_Qlo);
    cudaGetSymbolAddress((void**)&khi,  g_Khi);
    cudaGetSymbolAddress((void**)&klo,  g_Klo);
    cudaGetSymbolAddress((void**)&vthi, g_Vthi);
    cudaGetSymbolAddress((void**)&vtlo, g_Vtlo);

    cudaFuncSetAttribute(gemm_mma, cudaFuncAttributeMaxDynamicSharedMemorySize, GSMEM);
    cudaFuncSetAttribute(attn_mma, cudaFuncAttributeMaxDynamicSharedMemorySize, ATT_SMEM);

    convw_kernel<<<dim3(QKVFF / 32, HIDDEN / 32), 256>>>(W_in,  b1hi, b1lo, HIDDEN, QKVFF);
    convw_kernel<<<dim3(HIDDEN / 32, VFF / 32),   256>>>(W_out, b2hi, b2lo, VFF,    HIDDEN);

    ln_kernel<<<R_ROWS, 256>>>(x, ln_w, ln_b, a1hi, a1lo);

    gemm_mma<<<dim3(QKVFF / 128, R_ROWS / 128), 256, GSMEM>>>(
        a1hi, a1lo, b1hi, b1lo, h, HIDDEN, QKVFF);

    rope_gelu_kernel<<<R_ROWS, 256>>>(h, qhi, qlo, khi, klo, a2hi, a2lo);
    vsplit_kernel<<<dim3(LSEQ / 64, 32), 256>>>(h, vthi, vtlo);

    attn_mma<<<dim3(LSEQ / 128, 32), 256, ATT_SMEM>>>(
        qhi, qlo, khi, klo, vthi, vtlo, a2hi, a2lo);

    gemm_mma<<<dim3(HIDDEN / 128, R_ROWS / 128), 256, GSMEM>>>(
        a2hi, a2lo, b2hi, b2lo, out, VFF, HIDDEN);
}